// round 1
// baseline (speedup 1.0000x reference)
#include <cuda_runtime.h>
#include <cuda_fp16.h>
#include <cstdint>
#include <cstddef>

// ---------------------------------------------------------------------------
// CompressedLinear: out[b,s,o] = sum_i x[b,s,i] * (w_int8[o,i]*scale) + bias[o]
//   x:      [2,2048,4096] fp32  -> M=4096 rows, K=4096
//   w_int8: [11008,4096]  int32 (int8-range codes) -> N=11008, K-major
//   scale:  fp32 scalar
//   bias:   [11008] fp32
//   out:    [4096,11008] fp32
//
// Strategy (round 1): convert x -> fp16, w -> fp16 (exact for int8 codes),
// then a 3-stage cp.async pipelined mma.sync fp16 GEMM with fp32 accum.
// fp16 x-rounding gives rms rel err ~2.8e-4 < 1e-3 threshold.
// ---------------------------------------------------------------------------

namespace {
constexpr int M_DIM = 4096;     // B*S
constexpr int K_DIM = 4096;     // DIN
constexpr int N_DIM = 11008;    // DOUT

constexpr int BM = 128;
constexpr int BN = 128;
constexpr int BK = 64;
constexpr int STAGES = 3;
constexpr int NTHREADS = 256;

constexpr int A_STAGE_BYTES = BM * BK * 2;                 // 16 KB
constexpr int B_STAGE_BYTES = BN * BK * 2;                 // 16 KB
constexpr int STAGE_BYTES   = A_STAGE_BYTES + B_STAGE_BYTES; // 32 KB
constexpr int SMEM_BYTES    = STAGES * STAGE_BYTES;        // 96 KB
constexpr int KTILES        = K_DIM / BK;                  // 64
}

// Scratch (allocation-free rule: __device__ globals)
__device__ __half g_X[(size_t)M_DIM * K_DIM];   // 32 MB, row-major [M,K]
__device__ __half g_W[(size_t)N_DIM * K_DIM];   // 90 MB, row-major [N,K]

// ---------------------------------------------------------------------------
// Conversion kernels
// ---------------------------------------------------------------------------
__global__ void convert_x_kernel(const float* __restrict__ x) {
    size_t i = ((size_t)blockIdx.x * blockDim.x + threadIdx.x) * 4;
    float4 v = *reinterpret_cast<const float4*>(x + i);
    __half2 h0 = __floats2half2_rn(v.x, v.y);
    __half2 h1 = __floats2half2_rn(v.z, v.w);
    uint2 u;
    u.x = reinterpret_cast<uint32_t&>(h0);
    u.y = reinterpret_cast<uint32_t&>(h1);
    *reinterpret_cast<uint2*>(&g_X[i]) = u;
}

__global__ void convert_w_kernel(const int* __restrict__ w) {
    size_t i = ((size_t)blockIdx.x * blockDim.x + threadIdx.x) * 4;
    int4 v = *reinterpret_cast<const int4*>(w + i);
    __half2 h0 = __halves2half2(__int2half_rn(v.x), __int2half_rn(v.y));
    __half2 h1 = __halves2half2(__int2half_rn(v.z), __int2half_rn(v.w));
    uint2 u;
    u.x = reinterpret_cast<uint32_t&>(h0);
    u.y = reinterpret_cast<uint32_t&>(h1);
    *reinterpret_cast<uint2*>(&g_W[i]) = u;
}

// ---------------------------------------------------------------------------
// GEMM helpers
// ---------------------------------------------------------------------------
__device__ __forceinline__ uint32_t swz128(uint32_t byte_off) {
    // SW128: XOR bits[4:6] with bits[7:9] (row low bits) -> conflict-free
    return byte_off ^ ((byte_off >> 3) & 0x70);
}

__device__ __forceinline__ void cp_async16(uint32_t dst_smem, const void* src) {
    asm volatile("cp.async.cg.shared.global [%0], [%1], 16;\n"
                 :: "r"(dst_smem), "l"(src));
}

__device__ __forceinline__ void cp_commit() {
    asm volatile("cp.async.commit_group;\n");
}

template <int N>
__device__ __forceinline__ void cp_wait() {
    asm volatile("cp.async.wait_group %0;\n" :: "n"(N));
}

// ---------------------------------------------------------------------------
// GEMM kernel: block 128x128x64, 8 warps (2 M x 4 N), warp tile 64x32,
// mma.sync.m16n8k16 fp16->fp32.
// ---------------------------------------------------------------------------
__global__ __launch_bounds__(NTHREADS, 2)
void gemm_kernel(const float* __restrict__ scale_p,
                 const float* __restrict__ bias,
                 float* __restrict__ out) {
    extern __shared__ __align__(128) char smem_raw[];
    const uint32_t smem_base = (uint32_t)__cvta_generic_to_shared(smem_raw);

    const int tid  = threadIdx.x;
    const int warp = tid >> 5;
    const int lane = tid & 31;
    const int bx = blockIdx.x;   // N block (0..85)
    const int by = blockIdx.y;   // M block (0..31)

    const int warp_m = warp & 1;   // 0..1  (64 rows each)
    const int warp_n = warp >> 1;  // 0..3  (32 cols each)

    const int mRow0 = by * BM;
    const int nCol0 = bx * BN;

    float acc[4][4][4];
    #pragma unroll
    for (int i = 0; i < 4; ++i)
        #pragma unroll
        for (int j = 0; j < 4; ++j)
            #pragma unroll
            for (int k = 0; k < 4; ++k)
                acc[i][j][k] = 0.0f;

    // --- stage loader: 1024 16B chunks per tile, 256 threads -> 4 each ---
    auto load_stage = [&](int s, int kt) {
        const uint32_t aBase = smem_base + s * STAGE_BYTES;
        const uint32_t bBase = aBase + A_STAGE_BYTES;
        const int k0 = kt * BK;
        #pragma unroll
        for (int t = 0; t < 4; ++t) {
            int c   = tid + t * NTHREADS;     // 0..1023
            int row = c >> 3;                 // 0..127
            int col = c & 7;                  // 16B chunk within 128B row
            uint32_t off = swz128((uint32_t)(row * 128 + col * 16));
            cp_async16(aBase + off,
                       &g_X[(size_t)(mRow0 + row) * K_DIM + k0 + col * 8]);
        }
        #pragma unroll
        for (int t = 0; t < 4; ++t) {
            int c   = tid + t * NTHREADS;
            int row = c >> 3;
            int col = c & 7;
            uint32_t off = swz128((uint32_t)(row * 128 + col * 16));
            cp_async16(bBase + off,
                       &g_W[(size_t)(nCol0 + row) * K_DIM + k0 + col * 8]);
        }
    };

    // --- compute one K-tile from stage s ---
    auto mma_stage = [&](int s) {
        const uint32_t aBase = smem_base + s * STAGE_BYTES;
        const uint32_t bBase = aBase + A_STAGE_BYTES;
        #pragma unroll
        for (int ks = 0; ks < BK / 16; ++ks) {
            uint32_t af[4][4];
            uint32_t bf[4][2];
            // A: 4 m16 tiles, ldmatrix.x4 each
            //   lanes 0-7: rows 0-7 kchunk0 | 8-15: rows 8-15 kc0
            //   16-23: rows 0-7 kc1 | 24-31: rows 8-15 kc1
            #pragma unroll
            for (int mt = 0; mt < 4; ++mt) {
                int r = warp_m * 64 + mt * 16 + (lane & 15);
                uint32_t addr = aBase +
                    swz128((uint32_t)(r * 128 + ks * 32 + (lane >> 4) * 16));
                asm volatile(
                    "ldmatrix.sync.aligned.m8n8.x4.shared.b16 {%0,%1,%2,%3}, [%4];\n"
                    : "=r"(af[mt][0]), "=r"(af[mt][1]),
                      "=r"(af[mt][2]), "=r"(af[mt][3])
                    : "r"(addr));
            }
            // B: 2 x (pair of n8 tiles), ldmatrix.x4 each
            //   groups (n_off, kc) = (0,0) (0,1) (8,0) (8,1)
            #pragma unroll
            for (int p = 0; p < 2; ++p) {
                int n  = warp_n * 32 + p * 16 + (lane & 7) + ((lane >> 4) << 3);
                int kc = (lane >> 3) & 1;
                uint32_t addr = bBase +
                    swz128((uint32_t)(n * 128 + ks * 32 + kc * 16));
                asm volatile(
                    "ldmatrix.sync.aligned.m8n8.x4.shared.b16 {%0,%1,%2,%3}, [%4];\n"
                    : "=r"(bf[2 * p][0]), "=r"(bf[2 * p][1]),
                      "=r"(bf[2 * p + 1][0]), "=r"(bf[2 * p + 1][1])
                    : "r"(addr));
            }
            #pragma unroll
            for (int mt = 0; mt < 4; ++mt) {
                #pragma unroll
                for (int nt = 0; nt < 4; ++nt) {
                    asm volatile(
                        "mma.sync.aligned.m16n8k16.row.col.f32.f16.f16.f32 "
                        "{%0,%1,%2,%3}, {%4,%5,%6,%7}, {%8,%9}, {%0,%1,%2,%3};\n"
                        : "+f"(acc[mt][nt][0]), "+f"(acc[mt][nt][1]),
                          "+f"(acc[mt][nt][2]), "+f"(acc[mt][nt][3])
                        : "r"(af[mt][0]), "r"(af[mt][1]),
                          "r"(af[mt][2]), "r"(af[mt][3]),
                          "r"(bf[nt][0]), "r"(bf[nt][1]));
                }
            }
        }
    };

    // --- prologue: fill STAGES-1 stages ---
    #pragma unroll
    for (int s = 0; s < STAGES - 1; ++s) {
        load_stage(s, s);
        cp_commit();
    }

    // --- mainloop ---
    int cs = 0;              // compute stage
    int ps = STAGES - 1;     // prefetch stage
    #pragma unroll 1
    for (int kt = 0; kt < KTILES; ++kt) {
        cp_wait<STAGES - 2>();
        __syncthreads();
        int pf = kt + STAGES - 1;
        if (pf < KTILES) load_stage(ps, pf);
        cp_commit();
        mma_stage(cs);
        if (++cs == STAGES) cs = 0;
        if (++ps == STAGES) ps = 0;
    }

    // --- epilogue: out = acc*scale + bias ---
    const float scl = __ldg(scale_p);
    const int mBase = mRow0 + warp_m * 64;
    const int nBase = nCol0 + warp_n * 32;
    const int rl = lane >> 2;
    const int cl = (lane & 3) * 2;
    #pragma unroll
    for (int mt = 0; mt < 4; ++mt) {
        #pragma unroll
        for (int nt = 0; nt < 4; ++nt) {
            int c = nBase + nt * 8 + cl;
            float2 bv = *reinterpret_cast<const float2*>(bias + c);
            int r0 = mBase + mt * 16 + rl;
            float2 v0 = make_float2(acc[mt][nt][0] * scl + bv.x,
                                    acc[mt][nt][1] * scl + bv.y);
            *reinterpret_cast<float2*>(out + (size_t)r0 * N_DIM + c) = v0;
            float2 v1 = make_float2(acc[mt][nt][2] * scl + bv.x,
                                    acc[mt][nt][3] * scl + bv.y);
            *reinterpret_cast<float2*>(out + (size_t)(r0 + 8) * N_DIM + c) = v1;
        }
    }
}

// ---------------------------------------------------------------------------
// Launch
// ---------------------------------------------------------------------------
extern "C" void kernel_launch(void* const* d_in, const int* in_sizes, int n_in,
                              void* d_out, int out_size) {
    const float* x     = (const float*)d_in[0];
    const int*   w     = (const int*)d_in[1];
    const float* scale = (const float*)d_in[2];
    const float* bias  = (const float*)d_in[3];
    float* out = (float*)d_out;

    cudaFuncSetAttribute(gemm_kernel,
                         cudaFuncAttributeMaxDynamicSharedMemorySize,
                         SMEM_BYTES);

    // x: 16,777,216 elems / (4*256) = 16384 blocks (exact)
    convert_x_kernel<<<(int)(((size_t)M_DIM * K_DIM) / (4 * 256)), 256>>>(x);
    // w: 45,088,768 elems / (4*256) = 44032 blocks (exact)
    convert_w_kernel<<<(int)(((size_t)N_DIM * K_DIM) / (4 * 256)), 256>>>(w);

    dim3 grid(N_DIM / BN, M_DIM / BM);   // (86, 32)
    gemm_kernel<<<grid, NTHREADS, SMEM_BYTES>>>(scale, bias, out);
}